// round 4
// baseline (speedup 1.0000x reference)
#include <cuda_runtime.h>
#include <cuda_fp16.h>
#include <cstdint>

// ============================================================================
// Problem constants (shapes fixed by setup_inputs)
// ============================================================================
static constexpr int BD   = 32;    // batch
static constexpr int VV   = 4;     // views
static constexpr int PP   = 784;   // patches
static constexpr int DD   = 768;   // model dim
static constexpr int TT   = VV * PP;           // 3136
static constexpr size_t TOK = (size_t)BD * TT; // 100352 tokens
static constexpr int HH   = 8;
static constexpr int DH   = 96;

// ============================================================================
// PTX helpers (portable sm_80+ subset only)
// ============================================================================
__device__ __forceinline__ uint32_t smem_to_u32(const void* smem_ptr) {
    uint32_t addr;
    asm("{ .reg .u64 tmp; cvta.to.shared.u64 tmp, %1; cvt.u32.u64 %0, tmp; }"
        : "=r"(addr) : "l"(smem_ptr));
    return addr;
}

__device__ __forceinline__ void cp_async16(uint32_t saddr, const void* gptr) {
    asm volatile("cp.async.cg.shared.global [%0], [%1], 16;"
                 :: "r"(saddr), "l"(gptr) : "memory");
}
__device__ __forceinline__ void cp_commit() {
    asm volatile("cp.async.commit_group;" ::: "memory");
}
template<int N>
__device__ __forceinline__ void cp_wait() {
    asm volatile("cp.async.wait_group %0;" :: "n"(N) : "memory");
}

__device__ __forceinline__ void ldsm_x4(uint32_t* r, uint32_t addr) {
    asm volatile("ldmatrix.sync.aligned.m8n8.x4.shared.b16 {%0,%1,%2,%3}, [%4];"
                 : "=r"(r[0]), "=r"(r[1]), "=r"(r[2]), "=r"(r[3]) : "r"(addr));
}

__device__ __forceinline__ void mma16816(float* c, const uint32_t* a, const uint32_t* b) {
    asm volatile(
        "mma.sync.aligned.m16n8k16.row.col.f32.f16.f16.f32 "
        "{%0,%1,%2,%3},{%4,%5,%6,%7},{%8,%9},{%0,%1,%2,%3};"
        : "+f"(c[0]), "+f"(c[1]), "+f"(c[2]), "+f"(c[3])
        : "r"(a[0]), "r"(a[1]), "r"(a[2]), "r"(a[3]), "r"(b[0]), "r"(b[1]));
}

// ============================================================================
// Device scratch (static __device__ arrays; cudaMalloc is forbidden)
// ============================================================================
__device__ __half g_h16 [TOK * DD];          // LN1 output (fp16)
__device__ __half g_qkv [TOK * 3 * DD];      // QKV (fp16)
__device__ __half g_o16 [TOK * DD];          // attention output (fp16)
__device__ float  g_x1  [TOK * DD];          // x + attn proj (fp32)
__device__ __half g_h2  [TOK * DD];          // LN2 output (fp16)
__device__ __half g_ffn [TOK * 4 * DD];      // gelu(ffn1) (fp16)
__device__ __half g_wqkv[3 * DD * DD];
__device__ __half g_wout[DD * DD];
__device__ __half g_w1  [4 * DD * DD];
__device__ __half g_w2  [DD * 4 * DD];

// ============================================================================
// fp32 -> fp16 weight conversion
// ============================================================================
__global__ void f2h_kernel(const float* __restrict__ in, __half* __restrict__ out, int n) {
    int i = blockIdx.x * blockDim.x + threadIdx.x;
    int stride = gridDim.x * blockDim.x;
    for (; i < n; i += stride) out[i] = __float2half(in[i]);
}

// ============================================================================
// LayerNorm: fp32 input -> fp16 output. One block (192 thr) per row of 768.
// ============================================================================
__global__ void __launch_bounds__(192) ln_kernel(
    const float* __restrict__ x, const float* __restrict__ w,
    const float* __restrict__ bb, __half* __restrict__ out)
{
    size_t row = blockIdx.x;
    int t = threadIdx.x;
    float4 v = reinterpret_cast<const float4*>(x + row * DD)[t];
    float s  = v.x + v.y + v.z + v.w;
    float ss = v.x*v.x + v.y*v.y + v.z*v.z + v.w*v.w;
    #pragma unroll
    for (int off = 16; off; off >>= 1) {
        s  += __shfl_xor_sync(0xffffffffu, s,  off);
        ss += __shfl_xor_sync(0xffffffffu, ss, off);
    }
    __shared__ float rs_[6], rss_[6];
    int wi = t >> 5, ln = t & 31;
    if (ln == 0) { rs_[wi] = s; rss_[wi] = ss; }
    __syncthreads();
    float tot = 0.f, tot2 = 0.f;
    #pragma unroll
    for (int i = 0; i < 6; ++i) { tot += rs_[i]; tot2 += rss_[i]; }
    float mu  = tot * (1.0f / DD);
    float var = tot2 * (1.0f / DD) - mu * mu;
    float rstd = rsqrtf(var + 1e-5f);
    float4 wv = reinterpret_cast<const float4*>(w)[t];
    float4 bv = reinterpret_cast<const float4*>(bb)[t];
    __half2* op = reinterpret_cast<__half2*>(out + row * DD) + 2 * t;
    op[0] = __floats2half2_rn((v.x - mu) * rstd * wv.x + bv.x,
                              (v.y - mu) * rstd * wv.y + bv.y);
    op[1] = __floats2half2_rn((v.z - mu) * rstd * wv.z + bv.z,
                              (v.w - mu) * rstd * wv.w + bv.w);
}

// ============================================================================
// Cross-view attention: one warp per (b, p, head). V=4, dh=96 (3 dims/lane).
// ============================================================================
__global__ void __launch_bounds__(128) attn_kernel(
    const __half* __restrict__ qkv, __half* __restrict__ o)
{
    int wid = threadIdx.x >> 5, lane = threadIdx.x & 31;
    int g  = blockIdx.x * 4 + wid;
    int h  = g & 7;
    int bp = g >> 3;
    int b  = bp / PP, p = bp - b * PP;
    size_t rowbase = (size_t)b * TT + p;

    float q[4][3], k[4][3], vv[4][3];
    #pragma unroll
    for (int v = 0; v < 4; ++v) {
        const __half* r = qkv + (rowbase + (size_t)v * PP) * (3 * DD) + h * DH + lane;
        #pragma unroll
        for (int j = 0; j < 3; ++j) {
            q[v][j]  = __half2float(r[32 * j]);
            k[v][j]  = __half2float(r[DD + 32 * j]);
            vv[v][j] = __half2float(r[2 * DD + 32 * j]);
        }
    }
    float s[4][4];
    #pragma unroll
    for (int i = 0; i < 4; ++i) {
        #pragma unroll
        for (int j = 0; j < 4; ++j) {
            float acc = q[i][0]*k[j][0] + q[i][1]*k[j][1] + q[i][2]*k[j][2];
            #pragma unroll
            for (int off = 16; off; off >>= 1)
                acc += __shfl_xor_sync(0xffffffffu, acc, off);
            s[i][j] = acc * 0.1020620726f;   // 1/sqrt(96)
        }
    }
    #pragma unroll
    for (int i = 0; i < 4; ++i) {
        float m = fmaxf(fmaxf(s[i][0], s[i][1]), fmaxf(s[i][2], s[i][3]));
        float e0 = expf(s[i][0] - m), e1 = expf(s[i][1] - m);
        float e2 = expf(s[i][2] - m), e3 = expf(s[i][3] - m);
        float inv = 1.0f / (e0 + e1 + e2 + e3);
        __half* orow = o + (rowbase + (size_t)i * PP) * DD + h * DH + lane;
        #pragma unroll
        for (int j = 0; j < 3; ++j) {
            float ov = (e0 * vv[0][j] + e1 * vv[1][j] + e2 * vv[2][j] + e3 * vv[3][j]) * inv;
            orow[32 * j] = __float2half(ov);
        }
    }
}

// ============================================================================
// A-resident HMMA GEMM (K extent fixed = 768):
//   C[M, Ntot] (+)= A[M, K] @ W[Ntot, K]^T  with epilogue:
//     EPI 0: out fp16 = acc + bias
//     EPI 1: out fp16 = gelu_exact(acc + bias)
//     EPI 2: out fp32 = acc + bias + resid
//     EPI 3: out fp32 += acc                (split-K accumulate pass)
// One CTA owns a 128-row M block; A (128x768 fp16 = 192KB) lives in SMEM for
// the whole kernel (XOR-swizzled, ldmatrix conflict-free). B streamed in BK=32
// chunks through 3 stages (padded LDS=40). 512 thr = 16 warps of 32x32 tiles.
// ============================================================================
static constexpr int KEXT   = 768;
static constexpr int NKT    = KEXT / 32;               // 24
static constexpr int A_BYTES = 128 * KEXT * 2;         // 196608
static constexpr int LDS_B  = 40;                      // halves (32 + 8 pad)
static constexpr int B_STG  = 128 * LDS_B * 2;         // 10240 B
static constexpr int RSMEM  = A_BYTES + 3 * B_STG;     // 227328

// swizzled byte offset of (row r, half-index khalf) inside the A block
__device__ __forceinline__ uint32_t a_off(int r, int khalf) {
    int kb = khalf << 1;
    return (uint32_t)(r * (KEXT * 2) + (kb & ~127) + ((((kb >> 4) ^ r) & 7) << 4));
}

template<int EPI>
__global__ void __launch_bounds__(512, 1) gemm_res(
    const __half* __restrict__ A, const __half* __restrict__ W,
    const float* __restrict__ bias, const float* __restrict__ resid,
    void* __restrict__ outp, int strideA, int strideW, int Ntot, int NP)
{
    extern __shared__ char smem[];
    const uint32_t sA = smem_to_u32(smem);
    const uint32_t sB0 = sA + A_BYTES;
    int tid = threadIdx.x;
    int lane = tid & 31, wid = tid >> 5;
    int m0 = blockIdx.x * 128;
    int wm = (wid & 3) * 32;     // warp M offset in 128
    int wn = (wid >> 2) * 32;    // warp N offset in 128

    // ---- load resident A block: 12288 16B-chunks, 24 per thread ----
    #pragma unroll
    for (int i = 0; i < 24; ++i) {
        int id = tid + i * 512;
        int r = id / 96, cc = id % 96;      // 96 chunks per 768-half row
        cp_async16(sA + a_off(r, cc * 8),
                   A + (size_t)(m0 + r) * strideA + cc * 8);
    }
    cp_commit();

    // ---- B prefetch: one 16B chunk per thread per (pass, kt) ----
    int b_r = tid >> 2, b_c = tid & 3;
    auto prefetchB = [&](int g) {
        int np = g / NKT, kt = g - np * NKT, s = g % 3;
        cp_async16(sB0 + s * B_STG + (uint32_t)(b_r * LDS_B + b_c * 8) * 2,
                   W + (size_t)(np * 128 + b_r) * strideW + kt * 32 + b_c * 8);
    };
    prefetchB(0); cp_commit();
    prefetchB(1); cp_commit();

    // ldmatrix lane constants (fragment wiring validated in R3 kernel)
    int a_r    = wm + (lane & 15);
    int a_koff = (lane >> 4) << 3;
    int b_n    = wn + (lane & 7) + ((lane >> 4) << 3);
    int b_k    = ((lane >> 3) & 1) << 3;

    float c[2][4][4];
    #pragma unroll
    for (int i = 0; i < 2; ++i)
        #pragma unroll
        for (int j = 0; j < 4; ++j)
            #pragma unroll
            for (int r = 0; r < 4; ++r) c[i][j][r] = 0.f;

    const int G = NP * NKT;
    #pragma unroll 1
    for (int g = 0; g < G; ++g) {
        cp_wait<1>();
        __syncthreads();
        if (g + 2 < G) prefetchB(g + 2);
        cp_commit();

        int kt = g % NKT;
        uint32_t sB = sB0 + (g % 3) * B_STG;

        #pragma unroll
        for (int ks = 0; ks < 2; ++ks) {
            uint32_t a[2][4], b[2][4];
            int khalf = kt * 32 + ks * 16 + a_koff;
            #pragma unroll
            for (int ma = 0; ma < 2; ++ma)
                ldsm_x4(a[ma], sA + a_off(a_r + ma * 16, khalf));
            #pragma unroll
            for (int nb = 0; nb < 2; ++nb)
                ldsm_x4(b[nb], sB + (uint32_t)((b_n + nb * 16) * LDS_B + ks * 16 + b_k) * 2);
            #pragma unroll
            for (int ma = 0; ma < 2; ++ma)
                #pragma unroll
                for (int na = 0; na < 4; ++na)
                    mma16816(c[ma][na], a[ma], b[na >> 1] + (na & 1) * 2);
        }

        if (kt == NKT - 1) {
            // ---- epilogue for pass np (registers -> gmem), then reset acc ----
            int n0 = (g / NKT) * 128;
            #pragma unroll
            for (int ma = 0; ma < 2; ++ma) {
                int row = m0 + wm + ma * 16 + (lane >> 2);
                #pragma unroll
                for (int na = 0; na < 4; ++na) {
                    int col = n0 + wn + na * 8 + ((lane & 3) << 1);
                    float bb0 = 0.f, bb1 = 0.f;
                    if (EPI != 3) { bb0 = bias[col]; bb1 = bias[col + 1]; }
                    #pragma unroll
                    for (int h = 0; h < 2; ++h) {
                        size_t off = (size_t)(row + h * 8) * Ntot + col;
                        float v0 = c[ma][na][2 * h + 0] + bb0;
                        float v1 = c[ma][na][2 * h + 1] + bb1;
                        if (EPI == 1) {
                            v0 = 0.5f * v0 * (1.0f + erff(v0 * 0.70710678f));
                            v1 = 0.5f * v1 * (1.0f + erff(v1 * 0.70710678f));
                        }
                        if (EPI == 2) {
                            float2 r2 = *reinterpret_cast<const float2*>(resid + off);
                            *reinterpret_cast<float2*>(reinterpret_cast<float*>(outp) + off) =
                                make_float2(v0 + r2.x, v1 + r2.y);
                        } else if (EPI == 3) {
                            float* op = reinterpret_cast<float*>(outp) + off;
                            float2 r2 = *reinterpret_cast<const float2*>(op);
                            *reinterpret_cast<float2*>(op) = make_float2(v0 + r2.x, v1 + r2.y);
                        } else {
                            *reinterpret_cast<__half2*>(reinterpret_cast<__half*>(outp) + off) =
                                __floats2half2_rn(v0, v1);
                        }
                        c[ma][na][2 * h + 0] = 0.f;
                        c[ma][na][2 * h + 1] = 0.f;
                    }
                }
            }
        }
    }
}

// ============================================================================
// Host launch
// ============================================================================
extern "C" void kernel_launch(void* const* d_in, const int* in_sizes, int n_in,
                              void* d_out, int out_size)
{
    const float* x        = (const float*)d_in[0];
    // d_in[1] = num_views (scalar, fixed = 4)
    const float* norm1_w  = (const float*)d_in[2];
    const float* norm1_b  = (const float*)d_in[3];
    const float* in_proj_w= (const float*)d_in[4];
    const float* in_proj_b= (const float*)d_in[5];
    const float* out_w    = (const float*)d_in[6];
    const float* out_b    = (const float*)d_in[7];
    const float* norm2_w  = (const float*)d_in[8];
    const float* norm2_b  = (const float*)d_in[9];
    const float* ffn_w1   = (const float*)d_in[10];
    const float* ffn_b1   = (const float*)d_in[11];
    const float* ffn_w2   = (const float*)d_in[12];
    const float* ffn_b2   = (const float*)d_in[13];

    __half *h16, *qkv, *o16, *h2, *ffn, *wq, *wo, *w1, *w2;
    float* x1;
    cudaGetSymbolAddress((void**)&h16, g_h16);
    cudaGetSymbolAddress((void**)&qkv, g_qkv);
    cudaGetSymbolAddress((void**)&o16, g_o16);
    cudaGetSymbolAddress((void**)&x1,  g_x1);
    cudaGetSymbolAddress((void**)&h2,  g_h2);
    cudaGetSymbolAddress((void**)&ffn, g_ffn);
    cudaGetSymbolAddress((void**)&wq,  g_wqkv);
    cudaGetSymbolAddress((void**)&wo,  g_wout);
    cudaGetSymbolAddress((void**)&w1,  g_w1);
    cudaGetSymbolAddress((void**)&w2,  g_w2);

    cudaFuncSetAttribute(gemm_res<0>, cudaFuncAttributeMaxDynamicSharedMemorySize, RSMEM);
    cudaFuncSetAttribute(gemm_res<1>, cudaFuncAttributeMaxDynamicSharedMemorySize, RSMEM);
    cudaFuncSetAttribute(gemm_res<2>, cudaFuncAttributeMaxDynamicSharedMemorySize, RSMEM);
    cudaFuncSetAttribute(gemm_res<3>, cudaFuncAttributeMaxDynamicSharedMemorySize, RSMEM);

    const unsigned MT = (unsigned)(TOK / 128);   // 784 M-tiles

    // weight conversion fp32 -> fp16
    f2h_kernel<<<4608, 256>>>(in_proj_w, wq, 3 * DD * DD);
    f2h_kernel<<<2304, 256>>>(out_w,     wo, DD * DD);
    f2h_kernel<<<4608, 256>>>(ffn_w1,    w1, 4 * DD * DD);
    f2h_kernel<<<4608, 256>>>(ffn_w2,    w2, DD * 4 * DD);

    // LN1
    ln_kernel<<<(unsigned)TOK, 192>>>(x, norm1_w, norm1_b, h16);

    // QKV = LN1 @ Wqkv^T + b   (fp16 out, Ntot=2304, NP=18)
    gemm_res<0><<<MT, 512, RSMEM>>>(h16, wq, in_proj_b, nullptr, qkv,
                                    DD, DD, 3 * DD, 18);

    // cross-view attention
    attn_kernel<<<(BD * PP * HH) / 4, 128>>>(qkv, o16);

    // out proj + residual -> x1 (fp32, Ntot=768, NP=6)
    gemm_res<2><<<MT, 512, RSMEM>>>(o16, wo, out_b, x, x1,
                                    DD, DD, DD, 6);

    // LN2
    ln_kernel<<<(unsigned)TOK, 192>>>(x1, norm2_w, norm2_b, h2);

    // FFN1 + exact GELU (fp16 out, Ntot=3072, NP=24)
    gemm_res<1><<<MT, 512, RSMEM>>>(h2, w1, ffn_b1, nullptr, ffn,
                                    DD, DD, 4 * DD, 24);

    // FFN2 + residual -> d_out (fp32), split-K: 4 chunks of 768
    //   pass 0: bias + resid, passes 1..3: accumulate
    gemm_res<2><<<MT, 512, RSMEM>>>(ffn, w2, ffn_b2, x1, (float*)d_out,
                                    4 * DD, 4 * DD, DD, 6);
    for (int cchunk = 1; cchunk < 4; ++cchunk) {
        gemm_res<3><<<MT, 512, RSMEM>>>(ffn + cchunk * DD, w2 + cchunk * DD,
                                        nullptr, nullptr, (float*)d_out,
                                        4 * DD, 4 * DD, DD, 6);
    }

    (void)in_sizes; (void)n_in; (void)out_size;
}

// round 5
// speedup vs baseline: 1.3640x; 1.3640x over previous
#include <cuda_runtime.h>
#include <cuda_fp16.h>
#include <cstdint>

// ============================================================================
// Problem constants (shapes fixed by setup_inputs)
// ============================================================================
static constexpr int BD   = 32;    // batch
static constexpr int VV   = 4;     // views
static constexpr int PP   = 784;   // patches
static constexpr int DD   = 768;   // model dim
static constexpr int TT   = VV * PP;           // 3136
static constexpr size_t TOK = (size_t)BD * TT; // 100352 tokens
static constexpr int HH   = 8;
static constexpr int DH   = 96;

// ============================================================================
// PTX helpers (portable sm_80+ subset only)
// ============================================================================
__device__ __forceinline__ uint32_t smem_to_u32(const void* smem_ptr) {
    uint32_t addr;
    asm("{ .reg .u64 tmp; cvta.to.shared.u64 tmp, %1; cvt.u32.u64 %0, tmp; }"
        : "=r"(addr) : "l"(smem_ptr));
    return addr;
}

__device__ __forceinline__ void cp_async16(uint32_t saddr, const void* gptr) {
    asm volatile("cp.async.cg.shared.global [%0], [%1], 16;"
                 :: "r"(saddr), "l"(gptr) : "memory");
}
__device__ __forceinline__ void cp_commit() {
    asm volatile("cp.async.commit_group;" ::: "memory");
}
template<int N>
__device__ __forceinline__ void cp_wait() {
    asm volatile("cp.async.wait_group %0;" :: "n"(N) : "memory");
}

__device__ __forceinline__ void ldsm_x4(uint32_t* r, uint32_t addr) {
    asm volatile("ldmatrix.sync.aligned.m8n8.x4.shared.b16 {%0,%1,%2,%3}, [%4];"
                 : "=r"(r[0]), "=r"(r[1]), "=r"(r[2]), "=r"(r[3]) : "r"(addr));
}

__device__ __forceinline__ void mma16816(float* c, const uint32_t* a, const uint32_t* b) {
    asm volatile(
        "mma.sync.aligned.m16n8k16.row.col.f32.f16.f16.f32 "
        "{%0,%1,%2,%3},{%4,%5,%6,%7},{%8,%9},{%0,%1,%2,%3};"
        : "+f"(c[0]), "+f"(c[1]), "+f"(c[2]), "+f"(c[3])
        : "r"(a[0]), "r"(a[1]), "r"(a[2]), "r"(a[3]), "r"(b[0]), "r"(b[1]));
}

// ============================================================================
// Device scratch (static __device__ arrays; cudaMalloc is forbidden)
// ============================================================================
__device__ __half g_h16 [TOK * DD];          // LN1 output (fp16)
__device__ __half g_qkv [TOK * 3 * DD];      // QKV (fp16)
__device__ __half g_o16 [TOK * DD];          // attention output (fp16)
__device__ float  g_x1  [TOK * DD];          // x + attn proj (fp32)
__device__ __half g_h2  [TOK * DD];          // LN2 output (fp16)
__device__ __half g_ffn [TOK * 4 * DD];      // gelu(ffn1) (fp16)
__device__ __half g_wqkv[3 * DD * DD];
__device__ __half g_wout[DD * DD];
__device__ __half g_w1  [4 * DD * DD];
__device__ __half g_w2  [DD * 4 * DD];

// ============================================================================
// fp32 -> fp16 conversion of all four weight matrices in one launch
// ============================================================================
static constexpr int N_WQ = 3 * DD * DD;     // 1769472
static constexpr int N_WO = DD * DD;         // 589824
static constexpr int N_W1 = 4 * DD * DD;     // 2359296
static constexpr int N_W2 = DD * 4 * DD;     // 2359296

__global__ void f2h_all_kernel(const float* __restrict__ wq_f, const float* __restrict__ wo_f,
                               const float* __restrict__ w1_f, const float* __restrict__ w2_f,
                               __half* __restrict__ wq, __half* __restrict__ wo,
                               __half* __restrict__ w1, __half* __restrict__ w2) {
    int total = N_WQ + N_WO + N_W1 + N_W2;
    int stride = gridDim.x * blockDim.x;
    for (int i = blockIdx.x * blockDim.x + threadIdx.x; i < total; i += stride) {
        int j = i;
        if (j < N_WQ) { wq[j] = __float2half(wq_f[j]); continue; }
        j -= N_WQ;
        if (j < N_WO) { wo[j] = __float2half(wo_f[j]); continue; }
        j -= N_WO;
        if (j < N_W1) { w1[j] = __float2half(w1_f[j]); continue; }
        j -= N_W1;
        w2[j] = __float2half(w2_f[j]);
    }
}

// ============================================================================
// LayerNorm: fp32 input -> fp16 output. One block (192 thr) per row of 768.
// ============================================================================
__global__ void __launch_bounds__(192) ln_kernel(
    const float* __restrict__ x, const float* __restrict__ w,
    const float* __restrict__ bb, __half* __restrict__ out)
{
    size_t row = blockIdx.x;
    int t = threadIdx.x;
    float4 v = reinterpret_cast<const float4*>(x + row * DD)[t];
    float s  = v.x + v.y + v.z + v.w;
    float ss = v.x*v.x + v.y*v.y + v.z*v.z + v.w*v.w;
    #pragma unroll
    for (int off = 16; off; off >>= 1) {
        s  += __shfl_xor_sync(0xffffffffu, s,  off);
        ss += __shfl_xor_sync(0xffffffffu, ss, off);
    }
    __shared__ float rs_[6], rss_[6];
    int wi = t >> 5, ln = t & 31;
    if (ln == 0) { rs_[wi] = s; rss_[wi] = ss; }
    __syncthreads();
    float tot = 0.f, tot2 = 0.f;
    #pragma unroll
    for (int i = 0; i < 6; ++i) { tot += rs_[i]; tot2 += rss_[i]; }
    float mu  = tot * (1.0f / DD);
    float var = tot2 * (1.0f / DD) - mu * mu;
    float rstd = rsqrtf(var + 1e-5f);
    float4 wv = reinterpret_cast<const float4*>(w)[t];
    float4 bv = reinterpret_cast<const float4*>(bb)[t];
    __half2* op = reinterpret_cast<__half2*>(out + row * DD) + 2 * t;
    op[0] = __floats2half2_rn((v.x - mu) * rstd * wv.x + bv.x,
                              (v.y - mu) * rstd * wv.y + bv.y);
    op[1] = __floats2half2_rn((v.z - mu) * rstd * wv.z + bv.z,
                              (v.w - mu) * rstd * wv.w + bv.w);
}

// ============================================================================
// Cross-view attention: one warp per (b, p, head). V=4, dh=96 (3 dims/lane).
// ============================================================================
__global__ void __launch_bounds__(128) attn_kernel(
    const __half* __restrict__ qkv, __half* __restrict__ o)
{
    int wid = threadIdx.x >> 5, lane = threadIdx.x & 31;
    int g  = blockIdx.x * 4 + wid;
    int h  = g & 7;
    int bp = g >> 3;
    int b  = bp / PP, p = bp - b * PP;
    size_t rowbase = (size_t)b * TT + p;

    float q[4][3], k[4][3], vv[4][3];
    #pragma unroll
    for (int v = 0; v < 4; ++v) {
        const __half* r = qkv + (rowbase + (size_t)v * PP) * (3 * DD) + h * DH + lane;
        #pragma unroll
        for (int j = 0; j < 3; ++j) {
            q[v][j]  = __half2float(r[32 * j]);
            k[v][j]  = __half2float(r[DD + 32 * j]);
            vv[v][j] = __half2float(r[2 * DD + 32 * j]);
        }
    }
    float s[4][4];
    #pragma unroll
    for (int i = 0; i < 4; ++i) {
        #pragma unroll
        for (int j = 0; j < 4; ++j) {
            float acc = q[i][0]*k[j][0] + q[i][1]*k[j][1] + q[i][2]*k[j][2];
            #pragma unroll
            for (int off = 16; off; off >>= 1)
                acc += __shfl_xor_sync(0xffffffffu, acc, off);
            s[i][j] = acc * 0.1020620726f;   // 1/sqrt(96)
        }
    }
    #pragma unroll
    for (int i = 0; i < 4; ++i) {
        float m = fmaxf(fmaxf(s[i][0], s[i][1]), fmaxf(s[i][2], s[i][3]));
        float e0 = expf(s[i][0] - m), e1 = expf(s[i][1] - m);
        float e2 = expf(s[i][2] - m), e3 = expf(s[i][3] - m);
        float inv = 1.0f / (e0 + e1 + e2 + e3);
        __half* orow = o + (rowbase + (size_t)i * PP) * DD + h * DH + lane;
        #pragma unroll
        for (int j = 0; j < 3; ++j) {
            float ov = (e0 * vv[0][j] + e1 * vv[1][j] + e2 * vv[2][j] + e3 * vv[3][j]) * inv;
            orow[32 * j] = __float2half(ov);
        }
    }
}

// ============================================================================
// HMMA GEMM:  C[M,N] = A[M,K](fp16) @ W[N,K]^T(fp16) + bias, epilogue
//   EPI 0: out fp16 = acc + bias
//   EPI 1: out fp16 = gelu_exact(acc + bias)
//   EPI 2: out fp32 = acc + bias + resid
// CTA tile 128x128, BK=32, 256 thr (8 warps, 2x4 of 64x32 warp tiles),
// 4-stage cp.async pipeline (3 chunks in flight), padded SMEM (LDS=40).
// ============================================================================
static constexpr int LDS_   = 40;           // halves per smem row (32 + 8 pad)
static constexpr int OSTG   = 128 * LDS_;   // halves per operand per stage
static constexpr int NSTAGE = 4;
static constexpr int GSMEM  = NSTAGE * 2 * OSTG * 2; // bytes = 81920

template<int EPI>
__global__ void __launch_bounds__(256, 2) gemm_mma(
    const __half* __restrict__ A, const __half* __restrict__ W,
    const float* __restrict__ bias, const float* __restrict__ resid,
    void* __restrict__ outp, int K, int Ntot)
{
    extern __shared__ __half smem[];
    int tid = threadIdx.x;
    int lane = tid & 31, wid = tid >> 5;
    int m0 = blockIdx.y * 128;
    int n0 = blockIdx.x * 128;
    int wm = (wid & 1) * 64;       // warp row offset in tile
    int wn = (wid >> 1) * 32;      // warp col offset in tile

    // ---- async prefetch of one K-chunk into stage s ----
    auto prefetch = [&](int kt, int s) {
        __half* st = smem + s * (2 * OSTG);
        int row = tid >> 2, cc = tid & 3;
        #pragma unroll
        for (int h = 0; h < 2; ++h) {
            int r = row + h * 64;
            cp_async16(smem_to_u32(st + r * LDS_ + cc * 8),
                       A + (size_t)(m0 + r) * K + kt * 32 + cc * 8);
            cp_async16(smem_to_u32(st + OSTG + r * LDS_ + cc * 8),
                       W + (size_t)(n0 + r) * K + kt * 32 + cc * 8);
        }
    };

    float c[4][4][4];
    #pragma unroll
    for (int i = 0; i < 4; ++i)
        #pragma unroll
        for (int j = 0; j < 4; ++j)
            #pragma unroll
            for (int r = 0; r < 4; ++r) c[i][j][r] = 0.f;

    int NK = K >> 5;
    prefetch(0, 0); cp_commit();
    prefetch(1, 1); cp_commit();
    prefetch(2, 2); cp_commit();

    // ldmatrix lane addressing (constant per thread)
    int a_r  = wm + (lane & 15);
    int a_k  = (lane >> 4) << 3;
    int b_n  = wn + (lane & 7) + ((lane >> 4) << 3);
    int b_k  = ((lane >> 3) & 1) << 3;

    #pragma unroll 1
    for (int kt = 0; kt < NK; ++kt) {
        cp_wait<2>();
        __syncthreads();
        if (kt + 3 < NK) prefetch(kt + 3, (kt + 3) % NSTAGE);
        cp_commit();

        const __half* sA = smem + (kt % NSTAGE) * (2 * OSTG);
        const __half* sB = sA + OSTG;
        #pragma unroll
        for (int ks = 0; ks < 2; ++ks) {
            uint32_t a[4][4], b[2][4];
            #pragma unroll
            for (int ma = 0; ma < 4; ++ma)
                ldsm_x4(a[ma], smem_to_u32(sA + (a_r + ma * 16) * LDS_ + ks * 16 + a_k));
            #pragma unroll
            for (int nb = 0; nb < 2; ++nb)
                ldsm_x4(b[nb], smem_to_u32(sB + (b_n + nb * 16) * LDS_ + ks * 16 + b_k));
            #pragma unroll
            for (int ma = 0; ma < 4; ++ma)
                #pragma unroll
                for (int na = 0; na < 4; ++na)
                    mma16816(c[ma][na], a[ma], b[na >> 1] + (na & 1) * 2);
        }
    }

    // ---- epilogue straight from registers ----
    #pragma unroll
    for (int ma = 0; ma < 4; ++ma) {
        #pragma unroll
        for (int na = 0; na < 4; ++na) {
            int row = m0 + wm + ma * 16 + (lane >> 2);
            int col = n0 + wn + na * 8 + ((lane & 3) << 1);
            float b0 = bias[col], b1 = bias[col + 1];
            #pragma unroll
            for (int h = 0; h < 2; ++h) {
                size_t off = (size_t)(row + h * 8) * Ntot + col;
                float v0 = c[ma][na][2 * h + 0] + b0;
                float v1 = c[ma][na][2 * h + 1] + b1;
                if (EPI == 1) {
                    v0 = 0.5f * v0 * (1.0f + erff(v0 * 0.70710678f));
                    v1 = 0.5f * v1 * (1.0f + erff(v1 * 0.70710678f));
                }
                if (EPI == 2) {
                    float2 r2 = *reinterpret_cast<const float2*>(resid + off);
                    float2 o2 = make_float2(v0 + r2.x, v1 + r2.y);
                    *reinterpret_cast<float2*>(reinterpret_cast<float*>(outp) + off) = o2;
                } else {
                    *reinterpret_cast<__half2*>(reinterpret_cast<__half*>(outp) + off) =
                        __floats2half2_rn(v0, v1);
                }
            }
        }
    }
}

// ============================================================================
// Host launch
// ============================================================================
extern "C" void kernel_launch(void* const* d_in, const int* in_sizes, int n_in,
                              void* d_out, int out_size)
{
    const float* x        = (const float*)d_in[0];
    // d_in[1] = num_views (scalar, fixed = 4)
    const float* norm1_w  = (const float*)d_in[2];
    const float* norm1_b  = (const float*)d_in[3];
    const float* in_proj_w= (const float*)d_in[4];
    const float* in_proj_b= (const float*)d_in[5];
    const float* out_w    = (const float*)d_in[6];
    const float* out_b    = (const float*)d_in[7];
    const float* norm2_w  = (const float*)d_in[8];
    const float* norm2_b  = (const float*)d_in[9];
    const float* ffn_w1   = (const float*)d_in[10];
    const float* ffn_b1   = (const float*)d_in[11];
    const float* ffn_w2   = (const float*)d_in[12];
    const float* ffn_b2   = (const float*)d_in[13];

    __half *h16, *qkv, *o16, *h2, *ffn, *wq, *wo, *w1, *w2;
    float* x1;
    cudaGetSymbolAddress((void**)&h16, g_h16);
    cudaGetSymbolAddress((void**)&qkv, g_qkv);
    cudaGetSymbolAddress((void**)&o16, g_o16);
    cudaGetSymbolAddress((void**)&x1,  g_x1);
    cudaGetSymbolAddress((void**)&h2,  g_h2);
    cudaGetSymbolAddress((void**)&ffn, g_ffn);
    cudaGetSymbolAddress((void**)&wq,  g_wqkv);
    cudaGetSymbolAddress((void**)&wo,  g_wout);
    cudaGetSymbolAddress((void**)&w1,  g_w1);
    cudaGetSymbolAddress((void**)&w2,  g_w2);

    cudaFuncSetAttribute(gemm_mma<0>, cudaFuncAttributeMaxDynamicSharedMemorySize, GSMEM);
    cudaFuncSetAttribute(gemm_mma<1>, cudaFuncAttributeMaxDynamicSharedMemorySize, GSMEM);
    cudaFuncSetAttribute(gemm_mma<2>, cudaFuncAttributeMaxDynamicSharedMemorySize, GSMEM);

    // weight conversion fp32 -> fp16 (single launch)
    f2h_all_kernel<<<8192, 256>>>(in_proj_w, out_w, ffn_w1, ffn_w2, wq, wo, w1, w2);

    // LN1
    ln_kernel<<<(unsigned)TOK, 192>>>(x, norm1_w, norm1_b, h16);

    // QKV = LN1 @ Wqkv^T + b
    gemm_mma<0><<<dim3(3 * DD / 128, (unsigned)(TOK / 128)), 256, GSMEM>>>(
        h16, wq, in_proj_b, nullptr, qkv, DD, 3 * DD);

    // cross-view attention
    attn_kernel<<<(BD * PP * HH) / 4, 128>>>(qkv, o16);

    // out proj + residual -> x1
    gemm_mma<2><<<dim3(DD / 128, (unsigned)(TOK / 128)), 256, GSMEM>>>(
        o16, wo, out_b, x, x1, DD, DD);

    // LN2
    ln_kernel<<<(unsigned)TOK, 192>>>(x1, norm2_w, norm2_b, h2);

    // FFN1 + exact GELU
    gemm_mma<1><<<dim3(4 * DD / 128, (unsigned)(TOK / 128)), 256, GSMEM>>>(
        h2, w1, ffn_b1, nullptr, ffn, DD, 4 * DD);

    // FFN2 + residual -> d_out (fp32)
    gemm_mma<2><<<dim3(DD / 128, (unsigned)(TOK / 128)), 256, GSMEM>>>(
        ffn, w2, ffn_b2, x1, (float*)d_out, 4 * DD, DD);

    (void)in_sizes; (void)n_in; (void)out_size;
}

// round 6
// speedup vs baseline: 1.4641x; 1.0734x over previous
#include <cuda_runtime.h>
#include <cuda_fp16.h>
#include <cstdint>

// ============================================================================
// Problem constants (shapes fixed by setup_inputs)
// ============================================================================
static constexpr int BD   = 32;    // batch
static constexpr int VV   = 4;     // views
static constexpr int PP   = 784;   // patches
static constexpr int DD   = 768;   // model dim
static constexpr int TT   = VV * PP;           // 3136
static constexpr size_t TOK = (size_t)BD * TT; // 100352 tokens
static constexpr int HH   = 8;
static constexpr int DH   = 96;

// ============================================================================
// PTX helpers (portable sm_80+ subset only)
// ============================================================================
__device__ __forceinline__ uint32_t smem_to_u32(const void* smem_ptr) {
    uint32_t addr;
    asm("{ .reg .u64 tmp; cvta.to.shared.u64 tmp, %1; cvt.u32.u64 %0, tmp; }"
        : "=r"(addr) : "l"(smem_ptr));
    return addr;
}

__device__ __forceinline__ void cp_async16(uint32_t saddr, const void* gptr) {
    asm volatile("cp.async.cg.shared.global [%0], [%1], 16;"
                 :: "r"(saddr), "l"(gptr) : "memory");
}
__device__ __forceinline__ void cp_commit() {
    asm volatile("cp.async.commit_group;" ::: "memory");
}
template<int N>
__device__ __forceinline__ void cp_wait() {
    asm volatile("cp.async.wait_group %0;" :: "n"(N) : "memory");
}

__device__ __forceinline__ void ldsm_x4(uint32_t* r, uint32_t addr) {
    asm volatile("ldmatrix.sync.aligned.m8n8.x4.shared.b16 {%0,%1,%2,%3}, [%4];"
                 : "=r"(r[0]), "=r"(r[1]), "=r"(r[2]), "=r"(r[3]) : "r"(addr));
}

__device__ __forceinline__ void mma16816(float* c, const uint32_t* a, const uint32_t* b) {
    asm volatile(
        "mma.sync.aligned.m16n8k16.row.col.f32.f16.f16.f32 "
        "{%0,%1,%2,%3},{%4,%5,%6,%7},{%8,%9},{%0,%1,%2,%3};"
        : "+f"(c[0]), "+f"(c[1]), "+f"(c[2]), "+f"(c[3])
        : "r"(a[0]), "r"(a[1]), "r"(a[2]), "r"(a[3]), "r"(b[0]), "r"(b[1]));
}

// ============================================================================
// Device scratch (static __device__ arrays; cudaMalloc is forbidden)
// ============================================================================
__device__ __half g_h16 [TOK * DD];          // LN1 output (fp16)
__device__ __half g_qkv [TOK * 3 * DD];      // QKV (fp16)
__device__ __half g_o16 [TOK * DD];          // attention output (fp16)
__device__ float  g_x1  [TOK * DD];          // x + attn proj (fp32)
__device__ __half g_h2  [TOK * DD];          // LN2 output (fp16)
__device__ __half g_ffn [TOK * 4 * DD];      // gelu(ffn1) (fp16)
__device__ __half g_wqkv[3 * DD * DD];
__device__ __half g_wout[DD * DD];
__device__ __half g_w1  [4 * DD * DD];
__device__ __half g_w2  [DD * 4 * DD];

// ============================================================================
// fp32 -> fp16 conversion of all four weight matrices in one launch
// ============================================================================
static constexpr int N_WQ = 3 * DD * DD;
static constexpr int N_WO = DD * DD;
static constexpr int N_W1 = 4 * DD * DD;
static constexpr int N_W2 = DD * 4 * DD;

__global__ void f2h_all_kernel(const float* __restrict__ wq_f, const float* __restrict__ wo_f,
                               const float* __restrict__ w1_f, const float* __restrict__ w2_f,
                               __half* __restrict__ wq, __half* __restrict__ wo,
                               __half* __restrict__ w1, __half* __restrict__ w2) {
    int total = N_WQ + N_WO + N_W1 + N_W2;
    int stride = gridDim.x * blockDim.x;
    for (int i = blockIdx.x * blockDim.x + threadIdx.x; i < total; i += stride) {
        int j = i;
        if (j < N_WQ) { wq[j] = __float2half(wq_f[j]); continue; }
        j -= N_WQ;
        if (j < N_WO) { wo[j] = __float2half(wo_f[j]); continue; }
        j -= N_WO;
        if (j < N_W1) { w1[j] = __float2half(w1_f[j]); continue; }
        j -= N_W1;
        w2[j] = __float2half(w2_f[j]);
    }
}

// ============================================================================
// LayerNorm: fp32 input -> fp16 output. One block (192 thr) per row of 768.
// ============================================================================
__global__ void __launch_bounds__(192) ln_kernel(
    const float* __restrict__ x, const float* __restrict__ w,
    const float* __restrict__ bb, __half* __restrict__ out)
{
    size_t row = blockIdx.x;
    int t = threadIdx.x;
    float4 v = reinterpret_cast<const float4*>(x + row * DD)[t];
    float s  = v.x + v.y + v.z + v.w;
    float ss = v.x*v.x + v.y*v.y + v.z*v.z + v.w*v.w;
    #pragma unroll
    for (int off = 16; off; off >>= 1) {
        s  += __shfl_xor_sync(0xffffffffu, s,  off);
        ss += __shfl_xor_sync(0xffffffffu, ss, off);
    }
    __shared__ float rs_[6], rss_[6];
    int wi = t >> 5, ln = t & 31;
    if (ln == 0) { rs_[wi] = s; rss_[wi] = ss; }
    __syncthreads();
    float tot = 0.f, tot2 = 0.f;
    #pragma unroll
    for (int i = 0; i < 6; ++i) { tot += rs_[i]; tot2 += rss_[i]; }
    float mu  = tot * (1.0f / DD);
    float var = tot2 * (1.0f / DD) - mu * mu;
    float rstd = rsqrtf(var + 1e-5f);
    float4 wv = reinterpret_cast<const float4*>(w)[t];
    float4 bv = reinterpret_cast<const float4*>(bb)[t];
    __half2* op = reinterpret_cast<__half2*>(out + row * DD) + 2 * t;
    op[0] = __floats2half2_rn((v.x - mu) * rstd * wv.x + bv.x,
                              (v.y - mu) * rstd * wv.y + bv.y);
    op[1] = __floats2half2_rn((v.z - mu) * rstd * wv.z + bv.z,
                              (v.w - mu) * rstd * wv.w + bv.w);
}

// ============================================================================
// Cross-view attention: one warp per (b, p, head). V=4, dh=96 (3 dims/lane).
// ============================================================================
__global__ void __launch_bounds__(128) attn_kernel(
    const __half* __restrict__ qkv, __half* __restrict__ o)
{
    int wid = threadIdx.x >> 5, lane = threadIdx.x & 31;
    int g  = blockIdx.x * 4 + wid;
    int h  = g & 7;
    int bp = g >> 3;
    int b  = bp / PP, p = bp - b * PP;
    size_t rowbase = (size_t)b * TT + p;

    float q[4][3], k[4][3], vv[4][3];
    #pragma unroll
    for (int v = 0; v < 4; ++v) {
        const __half* r = qkv + (rowbase + (size_t)v * PP) * (3 * DD) + h * DH + lane;
        #pragma unroll
        for (int j = 0; j < 3; ++j) {
            q[v][j]  = __half2float(r[32 * j]);
            k[v][j]  = __half2float(r[DD + 32 * j]);
            vv[v][j] = __half2float(r[2 * DD + 32 * j]);
        }
    }
    float s[4][4];
    #pragma unroll
    for (int i = 0; i < 4; ++i) {
        #pragma unroll
        for (int j = 0; j < 4; ++j) {
            float acc = q[i][0]*k[j][0] + q[i][1]*k[j][1] + q[i][2]*k[j][2];
            #pragma unroll
            for (int off = 16; off; off >>= 1)
                acc += __shfl_xor_sync(0xffffffffu, acc, off);
            s[i][j] = acc * 0.1020620726f;   // 1/sqrt(96)
        }
    }
    #pragma unroll
    for (int i = 0; i < 4; ++i) {
        float m = fmaxf(fmaxf(s[i][0], s[i][1]), fmaxf(s[i][2], s[i][3]));
        float e0 = expf(s[i][0] - m), e1 = expf(s[i][1] - m);
        float e2 = expf(s[i][2] - m), e3 = expf(s[i][3] - m);
        float inv = 1.0f / (e0 + e1 + e2 + e3);
        __half* orow = o + (rowbase + (size_t)i * PP) * DD + h * DH + lane;
        #pragma unroll
        for (int j = 0; j < 3; ++j) {
            float ov = (e0 * vv[0][j] + e1 * vv[1][j] + e2 * vv[2][j] + e3 * vv[3][j]) * inv;
            orow[32 * j] = __float2half(ov);
        }
    }
}

// ============================================================================
// HMMA GEMM:  C[M,N] = A[M,K](fp16) @ W[N,K]^T(fp16) + bias, epilogue
//   EPI 0: out fp16 = acc + bias
//   EPI 1: out fp16 = gelu_exact(acc + bias)
//   EPI 2: out fp32 = acc + bias + resid
// CTA tile 128x128, BK=64 per stage, 256 thr (8 warps, 2x4 of 64x32 tiles),
// 3-stage cp.async pipeline (2 chunks in flight), padded SMEM (LDS=72,
// ldmatrix bank-conflict-free: row stride 144B -> bank 4r mod 32 distinct).
// ============================================================================
static constexpr int LDS_   = 72;            // halves per smem row (64 + 8 pad)
static constexpr int OSTG   = 128 * LDS_;    // halves per operand per stage
static constexpr int NSTAGE = 3;
static constexpr int GSMEM  = NSTAGE * 2 * OSTG * 2;   // 110592 bytes

template<int EPI>
__global__ void __launch_bounds__(256, 2) gemm_mma(
    const __half* __restrict__ A, const __half* __restrict__ W,
    const float* __restrict__ bias, const float* __restrict__ resid,
    void* __restrict__ outp, int K, int Ntot)
{
    extern __shared__ __half smem[];
    int tid = threadIdx.x;
    int lane = tid & 31, wid = tid >> 5;
    int m0 = blockIdx.y * 128;
    int n0 = blockIdx.x * 128;
    int wm = (wid & 1) * 64;       // warp row offset in tile
    int wn = (wid >> 1) * 32;      // warp col offset in tile

    // ---- async prefetch of one BK=64 chunk into stage s ----
    // 2048 16B-chunks per stage (2 operands x 128 rows x 8), 8 per thread
    auto prefetch = [&](int kt, int s) {
        __half* st = smem + s * (2 * OSTG);
        int r0 = tid >> 3, cc = tid & 7;
        #pragma unroll
        for (int h = 0; h < 4; ++h) {
            int r = r0 + h * 32;
            cp_async16(smem_to_u32(st + r * LDS_ + cc * 8),
                       A + (size_t)(m0 + r) * K + kt * 64 + cc * 8);
            cp_async16(smem_to_u32(st + OSTG + r * LDS_ + cc * 8),
                       W + (size_t)(n0 + r) * K + kt * 64 + cc * 8);
        }
    };

    float c[4][4][4];
    #pragma unroll
    for (int i = 0; i < 4; ++i)
        #pragma unroll
        for (int j = 0; j < 4; ++j)
            #pragma unroll
            for (int r = 0; r < 4; ++r) c[i][j][r] = 0.f;

    int NK = K >> 6;
    prefetch(0, 0); cp_commit();
    prefetch(1, 1); cp_commit();

    // ldmatrix lane addressing (constant per thread)
    int a_r  = wm + (lane & 15);
    int a_k  = (lane >> 4) << 3;
    int b_n  = wn + (lane & 7) + ((lane >> 4) << 3);
    int b_k  = ((lane >> 3) & 1) << 3;

    #pragma unroll 1
    for (int kt = 0; kt < NK; ++kt) {
        cp_wait<1>();
        __syncthreads();
        if (kt + 2 < NK) prefetch(kt + 2, (kt + 2) % NSTAGE);
        cp_commit();

        const __half* sA = smem + (kt % NSTAGE) * (2 * OSTG);
        const __half* sB = sA + OSTG;
        #pragma unroll
        for (int ks = 0; ks < 4; ++ks) {
            uint32_t a[4][4], b[2][4];
            #pragma unroll
            for (int ma = 0; ma < 4; ++ma)
                ldsm_x4(a[ma], smem_to_u32(sA + (a_r + ma * 16) * LDS_ + ks * 16 + a_k));
            #pragma unroll
            for (int nb = 0; nb < 2; ++nb)
                ldsm_x4(b[nb], smem_to_u32(sB + (b_n + nb * 16) * LDS_ + ks * 16 + b_k));
            #pragma unroll
            for (int ma = 0; ma < 4; ++ma)
                #pragma unroll
                for (int na = 0; na < 4; ++na)
                    mma16816(c[ma][na], a[ma], b[na >> 1] + (na & 1) * 2);
        }
    }

    // ---- epilogue straight from registers ----
    #pragma unroll
    for (int ma = 0; ma < 4; ++ma) {
        #pragma unroll
        for (int na = 0; na < 4; ++na) {
            int row = m0 + wm + ma * 16 + (lane >> 2);
            int col = n0 + wn + na * 8 + ((lane & 3) << 1);
            float b0 = bias[col], b1 = bias[col + 1];
            #pragma unroll
            for (int h = 0; h < 2; ++h) {
                size_t off = (size_t)(row + h * 8) * Ntot + col;
                float v0 = c[ma][na][2 * h + 0] + b0;
                float v1 = c[ma][na][2 * h + 1] + b1;
                if (EPI == 1) {
                    v0 = 0.5f * v0 * (1.0f + erff(v0 * 0.70710678f));
                    v1 = 0.5f * v1 * (1.0f + erff(v1 * 0.70710678f));
                }
                if (EPI == 2) {
                    float2 r2 = *reinterpret_cast<const float2*>(resid + off);
                    float2 o2 = make_float2(v0 + r2.x, v1 + r2.y);
                    *reinterpret_cast<float2*>(reinterpret_cast<float*>(outp) + off) = o2;
                } else {
                    *reinterpret_cast<__half2*>(reinterpret_cast<__half*>(outp) + off) =
                        __floats2half2_rn(v0, v1);
                }
            }
        }
    }
}

// ============================================================================
// Host launch
// ============================================================================
extern "C" void kernel_launch(void* const* d_in, const int* in_sizes, int n_in,
                              void* d_out, int out_size)
{
    const float* x        = (const float*)d_in[0];
    // d_in[1] = num_views (scalar, fixed = 4)
    const float* norm1_w  = (const float*)d_in[2];
    const float* norm1_b  = (const float*)d_in[3];
    const float* in_proj_w= (const float*)d_in[4];
    const float* in_proj_b= (const float*)d_in[5];
    const float* out_w    = (const float*)d_in[6];
    const float* out_b    = (const float*)d_in[7];
    const float* norm2_w  = (const float*)d_in[8];
    const float* norm2_b  = (const float*)d_in[9];
    const float* ffn_w1   = (const float*)d_in[10];
    const float* ffn_b1   = (const float*)d_in[11];
    const float* ffn_w2   = (const float*)d_in[12];
    const float* ffn_b2   = (const float*)d_in[13];

    __half *h16, *qkv, *o16, *h2, *ffn, *wq, *wo, *w1, *w2;
    float* x1;
    cudaGetSymbolAddress((void**)&h16, g_h16);
    cudaGetSymbolAddress((void**)&qkv, g_qkv);
    cudaGetSymbolAddress((void**)&o16, g_o16);
    cudaGetSymbolAddress((void**)&x1,  g_x1);
    cudaGetSymbolAddress((void**)&h2,  g_h2);
    cudaGetSymbolAddress((void**)&ffn, g_ffn);
    cudaGetSymbolAddress((void**)&wq,  g_wqkv);
    cudaGetSymbolAddress((void**)&wo,  g_wout);
    cudaGetSymbolAddress((void**)&w1,  g_w1);
    cudaGetSymbolAddress((void**)&w2,  g_w2);

    cudaFuncSetAttribute(gemm_mma<0>, cudaFuncAttributeMaxDynamicSharedMemorySize, GSMEM);
    cudaFuncSetAttribute(gemm_mma<1>, cudaFuncAttributeMaxDynamicSharedMemorySize, GSMEM);
    cudaFuncSetAttribute(gemm_mma<2>, cudaFuncAttributeMaxDynamicSharedMemorySize, GSMEM);

    // weight conversion fp32 -> fp16 (single launch)
    f2h_all_kernel<<<8192, 256>>>(in_proj_w, out_w, ffn_w1, ffn_w2, wq, wo, w1, w2);

    // LN1
    ln_kernel<<<(unsigned)TOK, 192>>>(x, norm1_w, norm1_b, h16);

    // QKV = LN1 @ Wqkv^T + b
    gemm_mma<0><<<dim3(3 * DD / 128, (unsigned)(TOK / 128)), 256, GSMEM>>>(
        h16, wq, in_proj_b, nullptr, qkv, DD, 3 * DD);

    // cross-view attention
    attn_kernel<<<(BD * PP * HH) / 4, 128>>>(qkv, o16);

    // out proj + residual -> x1
    gemm_mma<2><<<dim3(DD / 128, (unsigned)(TOK / 128)), 256, GSMEM>>>(
        o16, wo, out_b, x, x1, DD, DD);

    // LN2
    ln_kernel<<<(unsigned)TOK, 192>>>(x1, norm2_w, norm2_b, h2);

    // FFN1 + exact GELU
    gemm_mma<1><<<dim3(4 * DD / 128, (unsigned)(TOK / 128)), 256, GSMEM>>>(
        h2, w1, ffn_b1, nullptr, ffn, DD, 4 * DD);

    // FFN2 + residual -> d_out (fp32)
    gemm_mma<2><<<dim3(DD / 128, (unsigned)(TOK / 128)), 256, GSMEM>>>(
        ffn, w2, ffn_b2, x1, (float*)d_out, 4 * DD, DD);

    (void)in_sizes; (void)n_in; (void)out_size;
}